// round 1
// baseline (speedup 1.0000x reference)
#include <cuda_runtime.h>

// Problem dims (fixed by the reference)
static constexpr int Bb  = 2;
static constexpr int Tt  = 2048;
static constexpr int Cc  = 768;
static constexpr int NH  = 12;
static constexpr int HD  = 64;
static constexpr int C3  = 3 * Cc;   // 2304
static constexpr int MM  = Bb * Tt;  // 4096 rows

// Scratch (allocation-free rule: __device__ globals)
__device__ __align__(16) float g_qkv[(size_t)Bb * Tt * C3];  // [b,t,3c]
__device__ __align__(16) float g_att[(size_t)Bb * Tt * Cc];  // [b,t,c] attention output

// ---------------------------------------------------------------------------
// Tiled fp32 GEMM: C[M,N] = A[M,K] @ B[K,N], row-major.
// 128x64 tile, BK=16, 256 threads, 8x4 per-thread micro-tile.
// ---------------------------------------------------------------------------
template <int N, int K>
__device__ __forceinline__ void sgemm_body(const float* __restrict__ A,
                                           const float* __restrict__ B,
                                           float* __restrict__ C) {
    __shared__ float As[16][128];  // transposed A tile: As[k][m]
    __shared__ float Bs[16][64];

    const int tid  = threadIdx.x;
    const int tx   = tid & 15;        // 16 cols of threads -> 64 N
    const int ty   = tid >> 4;        // 16 rows of threads -> 128 M
    const int row0 = blockIdx.y * 128;
    const int col0 = blockIdx.x * 64;

    float acc[8][4];
#pragma unroll
    for (int i = 0; i < 8; i++)
#pragma unroll
        for (int j = 0; j < 4; j++) acc[i][j] = 0.f;

    for (int k0 = 0; k0 < K; k0 += 16) {
        // Load A tile (128x16) as float4 along K, store transposed.
#pragma unroll
        for (int t = 0; t < 2; t++) {
            int i  = tid + t * 256;
            int r  = i >> 2;
            int kk = (i & 3) << 2;
            float4 v = *(const float4*)(A + (size_t)(row0 + r) * K + k0 + kk);
            As[kk + 0][r] = v.x;
            As[kk + 1][r] = v.y;
            As[kk + 2][r] = v.z;
            As[kk + 3][r] = v.w;
        }
        // Load B tile (16x64) as float4.
        {
            int r  = tid >> 4;
            int nn = (tid & 15) << 2;
            *(float4*)&Bs[r][nn] = *(const float4*)(B + (size_t)(k0 + r) * N + col0 + nn);
        }
        __syncthreads();

#pragma unroll
        for (int k = 0; k < 16; k++) {
            float a[8], b[4];
            *(float4*)&a[0] = *(const float4*)&As[k][ty * 8];
            *(float4*)&a[4] = *(const float4*)&As[k][ty * 8 + 4];
            *(float4*)&b[0] = *(const float4*)&Bs[k][tx * 4];
#pragma unroll
            for (int i = 0; i < 8; i++)
#pragma unroll
                for (int j = 0; j < 4; j++)
                    acc[i][j] = fmaf(a[i], b[j], acc[i][j]);
        }
        __syncthreads();
    }

#pragma unroll
    for (int i = 0; i < 8; i++) {
        int row = row0 + ty * 8 + i;
        float4 v = {acc[i][0], acc[i][1], acc[i][2], acc[i][3]};
        *(float4*)(C + (size_t)row * N + col0 + tx * 4) = v;
    }
}

__global__ __launch_bounds__(256) void k_gemm_qkv(const float* __restrict__ x,
                                                  const float* __restrict__ Wqkv) {
    sgemm_body<C3, Cc>(x, Wqkv, g_qkv);
}

__global__ __launch_bounds__(256) void k_gemm_proj(const float* __restrict__ Wproj,
                                                   float* __restrict__ out) {
    sgemm_body<Cc, Cc>(g_att, Wproj, out);
}

// ---------------------------------------------------------------------------
// Causal flash attention, fp32.
// Grid: (T/64, NH, B). Block: 256 threads = 8 warps.
// Each warp owns 8 Q rows; each lane owns 2 score columns / 2 output dims.
// Online softmax, P staged via smem for the PV product.
// ---------------------------------------------------------------------------
static constexpr int SMEM_ATTN = (64 * 64 * 3 + 64 * 65) * (int)sizeof(float);  // 65792 B

__global__ __launch_bounds__(256) void k_attn() {
    extern __shared__ float sm[];
    float* Qs = sm;              // [64][64]
    float* Ks = Qs + 64 * 64;    // [64][65]  (pad -> 2-way max on reads)
    float* Vs = Ks + 64 * 65;    // [64][64]
    float* Ps = Vs + 64 * 64;    // [64][64]

    const int b   = blockIdx.z;
    const int h   = blockIdx.y;
    const int q0  = blockIdx.x * 64;
    const int tid = threadIdx.x;
    const int warp = tid >> 5;
    const int lane = tid & 31;
    const int wr  = warp * 8;     // first Q row (within tile) of this warp
    const int c0  = lane * 2;     // this lane's column pair

    const size_t base = (size_t)b * Tt * C3;

    // Load Q tile [64][64] (head h slice of the q third).
#pragma unroll
    for (int t = 0; t < 4; t++) {
        int i  = tid + t * 256;
        int r  = i >> 4;
        int dd = (i & 15) << 2;
        *(float4*)&Qs[r * 64 + dd] =
            *(const float4*)&g_qkv[base + (size_t)(q0 + r) * C3 + h * HD + dd];
    }

    float m[8], l[8], o[8][2];
#pragma unroll
    for (int r = 0; r < 8; r++) {
        m[r] = -1e30f; l[r] = 0.f; o[r][0] = 0.f; o[r][1] = 0.f;
    }

    const int ntiles = (q0 >> 6) + 1;  // causal: K tiles 0..q0/64 inclusive
    __syncthreads();

    for (int kt = 0; kt < ntiles; kt++) {
        const int k0 = kt * 64;

        // K tile -> Ks[c][d] (padded rows), scalar coalesced loads.
#pragma unroll
        for (int t = 0; t < 16; t++) {
            int i = tid + t * 256;
            int c = i >> 6;
            int d = i & 63;
            Ks[c * 65 + d] = g_qkv[base + (size_t)(k0 + c) * C3 + Cc + h * HD + d];
        }
        // V tile -> Vs[c][d], float4.
#pragma unroll
        for (int t = 0; t < 4; t++) {
            int i  = tid + t * 256;
            int c  = i >> 4;
            int dd = (i & 15) << 2;
            *(float4*)&Vs[c * 64 + dd] =
                *(const float4*)&g_qkv[base + (size_t)(k0 + c) * C3 + 2 * Cc + h * HD + dd];
        }
        __syncthreads();

        // S = Q K^T for this lane's 8 rows x 2 cols.
        float s[8][2];
#pragma unroll
        for (int r = 0; r < 8; r++) { s[r][0] = 0.f; s[r][1] = 0.f; }

#pragma unroll 8
        for (int d = 0; d < 64; d++) {
            float kv0 = Ks[c0 * 65 + d];
            float kv1 = Ks[(c0 + 1) * 65 + d];
#pragma unroll
            for (int r = 0; r < 8; r++) {
                float qv = Qs[(wr + r) * 64 + d];
                s[r][0] = fmaf(qv, kv0, s[r][0]);
                s[r][1] = fmaf(qv, kv1, s[r][1]);
            }
        }

        const bool diag = (k0 == q0);
#pragma unroll
        for (int r = 0; r < 8; r++) {
            float s0 = s[r][0] * 0.125f;  // 1/sqrt(64)
            float s1 = s[r][1] * 0.125f;
            if (diag) {
                if (c0 > wr + r)     s0 = -1e30f;
                if (c0 + 1 > wr + r) s1 = -1e30f;
            }
            // row max across the warp
            float mx = fmaxf(s0, s1);
#pragma unroll
            for (int off = 16; off > 0; off >>= 1)
                mx = fmaxf(mx, __shfl_xor_sync(0xffffffffu, mx, off));
            float mn  = fmaxf(m[r], mx);
            float scl = __expf(m[r] - mn);   // underflows to 0 on first tile
            float p0  = __expf(s0 - mn);
            float p1  = __expf(s1 - mn);
            float sum = p0 + p1;
#pragma unroll
            for (int off = 16; off > 0; off >>= 1)
                sum += __shfl_xor_sync(0xffffffffu, sum, off);
            l[r] = l[r] * scl + sum;
            m[r] = mn;
            o[r][0] *= scl;
            o[r][1] *= scl;
            Ps[(wr + r) * 64 + c0]     = p0;
            Ps[(wr + r) * 64 + c0 + 1] = p1;
        }
        __syncwarp();

        // O += P @ V  (lane owns dims c0, c0+1)
#pragma unroll 4
        for (int c = 0; c < 64; c++) {
            float2 vv = *(const float2*)&Vs[c * 64 + c0];
#pragma unroll
            for (int r = 0; r < 8; r++) {
                float p = Ps[(wr + r) * 64 + c];
                o[r][0] = fmaf(p, vv.x, o[r][0]);
                o[r][1] = fmaf(p, vv.y, o[r][1]);
            }
        }
        __syncthreads();  // protect Ks/Vs before next tile
    }

    // Normalize and write back in [b,t,c] layout (transpose folded in).
#pragma unroll
    for (int r = 0; r < 8; r++) {
        int t = q0 + wr + r;
        float inv = 1.0f / l[r];
        float2 v = {o[r][0] * inv, o[r][1] * inv};
        *(float2*)&g_att[(size_t)(b * Tt + t) * Cc + h * HD + c0] = v;
    }
}

// ---------------------------------------------------------------------------
// Launch: qkv GEMM -> attention -> proj GEMM
// Inputs (metadata order): x, mask (ignored; causality is analytic), Wqkv, Wproj
// ---------------------------------------------------------------------------
extern "C" void kernel_launch(void* const* d_in, const int* in_sizes, int n_in,
                              void* d_out, int out_size) {
    (void)in_sizes; (void)n_in; (void)out_size;
    const float* x     = (const float*)d_in[0];
    const float* Wqkv  = (const float*)d_in[2];
    const float* Wproj = (const float*)d_in[3];
    float* out = (float*)d_out;

    cudaFuncSetAttribute(k_attn, cudaFuncAttributeMaxDynamicSharedMemorySize, SMEM_ATTN);

    k_gemm_qkv<<<dim3(C3 / 64, MM / 128), 256>>>(x, Wqkv);
    k_attn<<<dim3(Tt / 64, NH, Bb), 256, SMEM_ATTN>>>();
    k_gemm_proj<<<dim3(Cc / 64, MM / 128), 256>>>(Wproj, out);
}

// round 12
// speedup vs baseline: 1.3159x; 1.3159x over previous
#include <cuda_runtime.h>
#include <cstdint>

// Problem dims (fixed by the reference)
static constexpr int Bb  = 2;
static constexpr int Tt  = 2048;
static constexpr int Cc  = 768;
static constexpr int NH  = 12;
static constexpr int HD  = 64;
static constexpr int C3  = 3 * Cc;   // 2304
static constexpr int MM  = Bb * Tt;  // 4096 rows
static constexpr int KK  = Cc;       // 768

// Scratch (allocation-free rule: __device__ globals)
__device__ __align__(16) float g_qkv[(size_t)Bb * Tt * C3];   // [b,t,3c]
__device__ __align__(16) float g_att[(size_t)Bb * Tt * Cc];   // [b,t,c]

// ---------------------------------------------------------------------------
// mma helpers
// ---------------------------------------------------------------------------
__device__ __forceinline__ uint32_t to_tf32(float v) {
    uint32_t r;
    asm("cvt.rna.tf32.f32 %0, %1;" : "=r"(r) : "f"(v));
    return r;
}
__device__ __forceinline__ void mma_tf32(float c[4], uint32_t a0, uint32_t a1, uint32_t a2,
                                         uint32_t a3, uint32_t b0, uint32_t b1) {
    asm volatile(
        "mma.sync.aligned.m16n8k8.row.col.f32.tf32.tf32.f32 "
        "{%0,%1,%2,%3}, {%4,%5,%6,%7}, {%8,%9}, {%0,%1,%2,%3};"
        : "+f"(c[0]), "+f"(c[1]), "+f"(c[2]), "+f"(c[3])
        : "r"(a0), "r"(a1), "r"(a2), "r"(a3), "r"(b0), "r"(b1));
}

// ---------------------------------------------------------------------------
// tf32 mma.sync GEMM reading B DIRECTLY from row-major W[K, N] (no transpose
// pre-pass). C[M,N] = A[M,768] @ W[768,N].
// CTA tile 128x128, BK=32, 256 threads (8 warps 2x4), warp tile 64x32.
// As: [128][36] m-major (k contig). Bs: [32][136] k-major (n contig).
// Smem 35,840 B (< 48 KB, no opt-in). Register double-buffered global loads.
// ---------------------------------------------------------------------------
static constexpr int BM = 128, BN = 128, BK = 32;
static constexpr int NCH  = KK / BK;   // 24
static constexpr int LDA  = 36;
static constexpr int LDB  = 136;
static constexpr int SMA  = BM * LDA;  // 4608 floats
static constexpr int SMB  = BK * LDB;  // 4352 floats
static constexpr int GSMQ = (SMA + SMB) * 4;  // 35840 bytes

template <int NTOT>
__device__ __forceinline__ void mmagemm_body(const float* __restrict__ A,
                                             const float* __restrict__ W,
                                             float* __restrict__ C) {
    extern __shared__ float sm[];
    float* As = sm;         // [BM][LDA]
    float* Bs = sm + SMA;   // [BK][LDB]

    const int tid  = threadIdx.x;
    const int lane = tid & 31;
    const int wid  = tid >> 5;
    const int wm   = wid & 1;   // 2 row groups of 64
    const int wn   = wid >> 1;  // 4 col groups of 32
    const int lm   = lane >> 2; // 0..7 (groupID)
    const int lk   = lane & 3;  // 0..3 (threadInGroup)

    const int row0 = blockIdx.y * BM;
    const int col0 = blockIdx.x * BN;
    const float* Ag = A + (size_t)row0 * KK;

    // A-load mapping: (row lrA + t*32, 16B chunk lqA)
    const int lrA = tid >> 3;  // 0..31
    const int lqA = tid & 7;   // 0..7
    // B-load mapping: (k-row lrB + t*8, n-chunk lqB)
    const int lrB = tid >> 5;  // 0..7
    const int lqB = tid & 31;  // 0..31

    float acc[4][4][4];
#pragma unroll
    for (int i = 0; i < 4; i++)
#pragma unroll
        for (int j = 0; j < 4; j++)
#pragma unroll
            for (int r = 0; r < 4; r++) acc[i][j][r] = 0.f;

    float4 pa[4], pb[4];
#pragma unroll
    for (int t = 0; t < 4; t++) {
        pa[t] = *(const float4*)(Ag + (size_t)(lrA + t * 32) * KK + lqA * 4);
        pb[t] = *(const float4*)(W + (size_t)(lrB + t * 8) * NTOT + col0 + lqB * 4);
    }

    for (int ch = 0; ch < NCH; ch++) {
#pragma unroll
        for (int t = 0; t < 4; t++) {
            *(float4*)(As + (lrA + t * 32) * LDA + lqA * 4) = pa[t];
            *(float4*)(Bs + (lrB + t * 8) * LDB + lqB * 4) = pb[t];
        }
        __syncthreads();

        if (ch + 1 < NCH) {
            const int k1 = (ch + 1) * BK;
#pragma unroll
            for (int t = 0; t < 4; t++) {
                pa[t] = *(const float4*)(Ag + (size_t)(lrA + t * 32) * KK + k1 + lqA * 4);
                pb[t] = *(const float4*)(W + (size_t)(k1 + lrB + t * 8) * NTOT + col0 + lqB * 4);
            }
        }

#pragma unroll
        for (int ks = 0; ks < 4; ks++) {
            const int kb = ks * 8 + lk;  // this lane's k for a0/b0; +4 for a2/b1
            uint32_t af[4][4], bf[4][2];
#pragma unroll
            for (int i = 0; i < 4; i++) {
                int m0 = wm * 64 + i * 16 + lm;
                af[i][0] = to_tf32(As[m0 * LDA + kb]);
                af[i][1] = to_tf32(As[(m0 + 8) * LDA + kb]);
                af[i][2] = to_tf32(As[m0 * LDA + kb + 4]);
                af[i][3] = to_tf32(As[(m0 + 8) * LDA + kb + 4]);
            }
#pragma unroll
            for (int j = 0; j < 4; j++) {
                int n0 = wn * 32 + j * 8 + lm;
                bf[j][0] = to_tf32(Bs[kb * LDB + n0]);
                bf[j][1] = to_tf32(Bs[(kb + 4) * LDB + n0]);
            }
#pragma unroll
            for (int i = 0; i < 4; i++)
#pragma unroll
                for (int j = 0; j < 4; j++)
                    mma_tf32(acc[i][j], af[i][0], af[i][1], af[i][2], af[i][3],
                             bf[j][0], bf[j][1]);
        }
        __syncthreads();
    }

    // Epilogue: c0,c1 at (row, col..col+1); c2,c3 at (row+8, same cols).
#pragma unroll
    for (int i = 0; i < 4; i++) {
#pragma unroll
        for (int j = 0; j < 4; j++) {
            int row = row0 + wm * 64 + i * 16 + lm;
            int col = col0 + wn * 32 + j * 8 + 2 * lk;
            float2 v0 = {acc[i][j][0], acc[i][j][1]};
            float2 v1 = {acc[i][j][2], acc[i][j][3]};
            *(float2*)(C + (size_t)row * NTOT + col)       = v0;
            *(float2*)(C + (size_t)(row + 8) * NTOT + col) = v1;
        }
    }
}

__global__ __launch_bounds__(256) void k_mmagemm_qkv(const float* __restrict__ x,
                                                     const float* __restrict__ Wqkv) {
    mmagemm_body<C3>(x, Wqkv, g_qkv);
}

// ---------------------------------------------------------------------------
// Round-1 SGEMM (proven): C[M,N] = A[M,K] @ B[K,N], row-major.
// 128x64 tile, BK=16, 256 threads, 8x4 micro-tile. Used for the proj GEMM.
// ---------------------------------------------------------------------------
template <int N, int K>
__device__ __forceinline__ void sgemm_body(const float* __restrict__ A,
                                           const float* __restrict__ B,
                                           float* __restrict__ C) {
    __shared__ float As[16][128];
    __shared__ float Bsm[16][64];

    const int tid  = threadIdx.x;
    const int tx   = tid & 15;
    const int ty   = tid >> 4;
    const int row0 = blockIdx.y * 128;
    const int col0 = blockIdx.x * 64;

    float acc[8][4];
#pragma unroll
    for (int i = 0; i < 8; i++)
#pragma unroll
        for (int j = 0; j < 4; j++) acc[i][j] = 0.f;

    for (int k0 = 0; k0 < K; k0 += 16) {
#pragma unroll
        for (int t = 0; t < 2; t++) {
            int i  = tid + t * 256;
            int r  = i >> 2;
            int kk = (i & 3) << 2;
            float4 v = *(const float4*)(A + (size_t)(row0 + r) * K + k0 + kk);
            As[kk + 0][r] = v.x;
            As[kk + 1][r] = v.y;
            As[kk + 2][r] = v.z;
            As[kk + 3][r] = v.w;
        }
        {
            int r  = tid >> 4;
            int nn = (tid & 15) << 2;
            *(float4*)&Bsm[r][nn] = *(const float4*)(B + (size_t)(k0 + r) * N + col0 + nn);
        }
        __syncthreads();

#pragma unroll
        for (int k = 0; k < 16; k++) {
            float a[8], b[4];
            *(float4*)&a[0] = *(const float4*)&As[k][ty * 8];
            *(float4*)&a[4] = *(const float4*)&As[k][ty * 8 + 4];
            *(float4*)&b[0] = *(const float4*)&Bsm[k][tx * 4];
#pragma unroll
            for (int i = 0; i < 8; i++)
#pragma unroll
                for (int j = 0; j < 4; j++)
                    acc[i][j] = fmaf(a[i], b[j], acc[i][j]);
        }
        __syncthreads();
    }

#pragma unroll
    for (int i = 0; i < 8; i++) {
        int row = row0 + ty * 8 + i;
        float4 v = {acc[i][0], acc[i][1], acc[i][2], acc[i][3]};
        *(float4*)(C + (size_t)row * N + col0 + tx * 4) = v;
    }
}

__global__ __launch_bounds__(256) void k_gemm_proj(const float* __restrict__ Wproj,
                                                   float* __restrict__ out) {
    sgemm_body<Cc, Cc>(g_att, Wproj, out);
}

// ---------------------------------------------------------------------------
// Causal flash attention, fp32 (byte-identical to the round-1 passing version).
// ---------------------------------------------------------------------------
static constexpr int SMEM_ATTN = (64 * 64 * 3 + 64 * 65) * (int)sizeof(float);

__global__ __launch_bounds__(256) void k_attn() {
    extern __shared__ float sm[];
    float* Qs = sm;
    float* Ks = Qs + 64 * 64;
    float* Vs = Ks + 64 * 65;
    float* Ps = Vs + 64 * 64;

    const int b   = blockIdx.z;
    const int h   = blockIdx.y;
    const int q0  = blockIdx.x * 64;
    const int tid = threadIdx.x;
    const int warp = tid >> 5;
    const int lane = tid & 31;
    const int wr  = warp * 8;
    const int c0  = lane * 2;

    const size_t base = (size_t)b * Tt * C3;

#pragma unroll
    for (int t = 0; t < 4; t++) {
        int i  = tid + t * 256;
        int r  = i >> 4;
        int dd = (i & 15) << 2;
        *(float4*)&Qs[r * 64 + dd] =
            *(const float4*)&g_qkv[base + (size_t)(q0 + r) * C3 + h * HD + dd];
    }

    float m[8], l[8], o[8][2];
#pragma unroll
    for (int r = 0; r < 8; r++) { m[r] = -1e30f; l[r] = 0.f; o[r][0] = 0.f; o[r][1] = 0.f; }

    const int ntiles = (q0 >> 6) + 1;
    __syncthreads();

    for (int kt = 0; kt < ntiles; kt++) {
        const int k0 = kt * 64;
#pragma unroll
        for (int t = 0; t < 16; t++) {
            int i = tid + t * 256;
            int c = i >> 6;
            int d = i & 63;
            Ks[c * 65 + d] = g_qkv[base + (size_t)(k0 + c) * C3 + Cc + h * HD + d];
        }
#pragma unroll
        for (int t = 0; t < 4; t++) {
            int i  = tid + t * 256;
            int c  = i >> 4;
            int dd = (i & 15) << 2;
            *(float4*)&Vs[c * 64 + dd] =
                *(const float4*)&g_qkv[base + (size_t)(k0 + c) * C3 + 2 * Cc + h * HD + dd];
        }
        __syncthreads();

        float s[8][2];
#pragma unroll
        for (int r = 0; r < 8; r++) { s[r][0] = 0.f; s[r][1] = 0.f; }

#pragma unroll 8
        for (int d = 0; d < 64; d++) {
            float kv0 = Ks[c0 * 65 + d];
            float kv1 = Ks[(c0 + 1) * 65 + d];
#pragma unroll
            for (int r = 0; r < 8; r++) {
                float qv = Qs[(wr + r) * 64 + d];
                s[r][0] = fmaf(qv, kv0, s[r][0]);
                s[r][1] = fmaf(qv, kv1, s[r][1]);
            }
        }

        const bool diag = (k0 == q0);
#pragma unroll
        for (int r = 0; r < 8; r++) {
            float s0 = s[r][0] * 0.125f;
            float s1 = s[r][1] * 0.125f;
            if (diag) {
                if (c0 > wr + r)     s0 = -1e30f;
                if (c0 + 1 > wr + r) s1 = -1e30f;
            }
            float mx = fmaxf(s0, s1);
#pragma unroll
            for (int off = 16; off > 0; off >>= 1)
                mx = fmaxf(mx, __shfl_xor_sync(0xffffffffu, mx, off));
            float mn  = fmaxf(m[r], mx);
            float scl = __expf(m[r] - mn);
            float p0  = __expf(s0 - mn);
            float p1  = __expf(s1 - mn);
            float sum = p0 + p1;
#pragma unroll
            for (int off = 16; off > 0; off >>= 1)
                sum += __shfl_xor_sync(0xffffffffu, sum, off);
            l[r] = l[r] * scl + sum;
            m[r] = mn;
            o[r][0] *= scl;
            o[r][1] *= scl;
            Ps[(wr + r) * 64 + c0]     = p0;
            Ps[(wr + r) * 64 + c0 + 1] = p1;
        }
        __syncwarp();

#pragma unroll 4
        for (int c = 0; c < 64; c++) {
            float2 vv = *(const float2*)&Vs[c * 64 + c0];
#pragma unroll
            for (int r = 0; r < 8; r++) {
                float p = Ps[(wr + r) * 64 + c];
                o[r][0] = fmaf(p, vv.x, o[r][0]);
                o[r][1] = fmaf(p, vv.y, o[r][1]);
            }
        }
        __syncthreads();
    }

#pragma unroll
    for (int r = 0; r < 8; r++) {
        int t = q0 + wr + r;
        float inv = 1.0f / l[r];
        float2 v = {o[r][0] * inv, o[r][1] * inv};
        *(float2*)&g_att[(size_t)(b * Tt + t) * Cc + h * HD + c0] = v;
    }
}

// ---------------------------------------------------------------------------
// Launch: qkv GEMM (tf32 mma, direct-B) -> attention -> proj GEMM (sgemm)
// Inputs (metadata order): x, mask (ignored; causality analytic), Wqkv, Wproj
// ---------------------------------------------------------------------------
extern "C" void kernel_launch(void* const* d_in, const int* in_sizes, int n_in,
                              void* d_out, int out_size) {
    (void)in_sizes; (void)n_in; (void)out_size;
    const float* x     = (const float*)d_in[0];
    const float* Wqkv  = (const float*)d_in[2];
    const float* Wproj = (const float*)d_in[3];
    float* out = (float*)d_out;

    cudaFuncSetAttribute(k_attn, cudaFuncAttributeMaxDynamicSharedMemorySize, SMEM_ATTN);

    k_mmagemm_qkv<<<dim3(C3 / BN, MM / BM), 256, GSMQ>>>(x, Wqkv);
    k_attn<<<dim3(Tt / 64, NH, Bb), 256, SMEM_ATTN>>>();
    k_gemm_proj<<<dim3(Cc / 64, MM / 128), 256>>>(Wproj, out);
}

// round 13
// speedup vs baseline: 2.8928x; 2.1984x over previous
#include <cuda_runtime.h>
#include <cstdint>

// Problem dims (fixed by the reference)
static constexpr int Bb  = 2;
static constexpr int Tt  = 2048;
static constexpr int Cc  = 768;
static constexpr int NH  = 12;
static constexpr int HD  = 64;
static constexpr int C3  = 3 * Cc;   // 2304
static constexpr int MM  = Bb * Tt;  // 4096 rows
static constexpr int KK  = Cc;       // 768

// Scratch (allocation-free rule: __device__ globals)
__device__ __align__(16) float g_qkv[(size_t)Bb * Tt * C3];   // [b,t,3c]
__device__ __align__(16) float g_att[(size_t)Bb * Tt * Cc];   // [b,t,c]

// ---------------------------------------------------------------------------
// mma helpers
// ---------------------------------------------------------------------------
__device__ __forceinline__ uint32_t to_tf32(float v) {
    uint32_t r;
    asm("cvt.rna.tf32.f32 %0, %1;" : "=r"(r) : "f"(v));
    return r;
}
__device__ __forceinline__ void mma_tf32(float c[4], uint32_t a0, uint32_t a1, uint32_t a2,
                                         uint32_t a3, uint32_t b0, uint32_t b1) {
    asm volatile(
        "mma.sync.aligned.m16n8k8.row.col.f32.tf32.tf32.f32 "
        "{%0,%1,%2,%3}, {%4,%5,%6,%7}, {%8,%9}, {%0,%1,%2,%3};"
        : "+f"(c[0]), "+f"(c[1]), "+f"(c[2]), "+f"(c[3])
        : "r"(a0), "r"(a1), "r"(a2), "r"(a3), "r"(b0), "r"(b1));
}

// ---------------------------------------------------------------------------
// tf32 mma.sync GEMM reading B DIRECTLY from row-major W[K, N].
// C[M,N] = A[M,768] @ W[768,N]. (Validated round 12.)
// ---------------------------------------------------------------------------
static constexpr int BM = 128, BN = 128, BK = 32;
static constexpr int NCH  = KK / BK;   // 24
static constexpr int LDA  = 36;
static constexpr int LDB  = 136;
static constexpr int SMA  = BM * LDA;
static constexpr int SMB  = BK * LDB;
static constexpr int GSMQ = (SMA + SMB) * 4;  // 35840 bytes

template <int NTOT>
__device__ __forceinline__ void mmagemm_body(const float* __restrict__ A,
                                             const float* __restrict__ W,
                                             float* __restrict__ C) {
    extern __shared__ float sm[];
    float* As = sm;         // [BM][LDA]
    float* Bs = sm + SMA;   // [BK][LDB]

    const int tid  = threadIdx.x;
    const int lane = tid & 31;
    const int wid  = tid >> 5;
    const int wm   = wid & 1;
    const int wn   = wid >> 1;
    const int lm   = lane >> 2;
    const int lk   = lane & 3;

    const int row0 = blockIdx.y * BM;
    const int col0 = blockIdx.x * BN;
    const float* Ag = A + (size_t)row0 * KK;

    const int lrA = tid >> 3;
    const int lqA = tid & 7;
    const int lrB = tid >> 5;
    const int lqB = tid & 31;

    float acc[4][4][4];
#pragma unroll
    for (int i = 0; i < 4; i++)
#pragma unroll
        for (int j = 0; j < 4; j++)
#pragma unroll
            for (int r = 0; r < 4; r++) acc[i][j][r] = 0.f;

    float4 pa[4], pb[4];
#pragma unroll
    for (int t = 0; t < 4; t++) {
        pa[t] = *(const float4*)(Ag + (size_t)(lrA + t * 32) * KK + lqA * 4);
        pb[t] = *(const float4*)(W + (size_t)(lrB + t * 8) * NTOT + col0 + lqB * 4);
    }

    for (int ch = 0; ch < NCH; ch++) {
#pragma unroll
        for (int t = 0; t < 4; t++) {
            *(float4*)(As + (lrA + t * 32) * LDA + lqA * 4) = pa[t];
            *(float4*)(Bs + (lrB + t * 8) * LDB + lqB * 4) = pb[t];
        }
        __syncthreads();

        if (ch + 1 < NCH) {
            const int k1 = (ch + 1) * BK;
#pragma unroll
            for (int t = 0; t < 4; t++) {
                pa[t] = *(const float4*)(Ag + (size_t)(lrA + t * 32) * KK + k1 + lqA * 4);
                pb[t] = *(const float4*)(W + (size_t)(k1 + lrB + t * 8) * NTOT + col0 + lqB * 4);
            }
        }

#pragma unroll
        for (int ks = 0; ks < 4; ks++) {
            const int kb = ks * 8 + lk;
            uint32_t af[4][4], bf[4][2];
#pragma unroll
            for (int i = 0; i < 4; i++) {
                int m0 = wm * 64 + i * 16 + lm;
                af[i][0] = to_tf32(As[m0 * LDA + kb]);
                af[i][1] = to_tf32(As[(m0 + 8) * LDA + kb]);
                af[i][2] = to_tf32(As[m0 * LDA + kb + 4]);
                af[i][3] = to_tf32(As[(m0 + 8) * LDA + kb + 4]);
            }
#pragma unroll
            for (int j = 0; j < 4; j++) {
                int n0 = wn * 32 + j * 8 + lm;
                bf[j][0] = to_tf32(Bs[kb * LDB + n0]);
                bf[j][1] = to_tf32(Bs[(kb + 4) * LDB + n0]);
            }
#pragma unroll
            for (int i = 0; i < 4; i++)
#pragma unroll
                for (int j = 0; j < 4; j++)
                    mma_tf32(acc[i][j], af[i][0], af[i][1], af[i][2], af[i][3],
                             bf[j][0], bf[j][1]);
        }
        __syncthreads();
    }

#pragma unroll
    for (int i = 0; i < 4; i++) {
#pragma unroll
        for (int j = 0; j < 4; j++) {
            int row = row0 + wm * 64 + i * 16 + lm;
            int col = col0 + wn * 32 + j * 8 + 2 * lk;
            float2 v0 = {acc[i][j][0], acc[i][j][1]};
            float2 v1 = {acc[i][j][2], acc[i][j][3]};
            *(float2*)(C + (size_t)row * NTOT + col)       = v0;
            *(float2*)(C + (size_t)(row + 8) * NTOT + col) = v1;
        }
    }
}

__global__ __launch_bounds__(256) void k_mmagemm_qkv(const float* __restrict__ x,
                                                     const float* __restrict__ Wqkv) {
    mmagemm_body<C3>(x, Wqkv, g_qkv);
}
__global__ __launch_bounds__(256) void k_mmagemm_proj(const float* __restrict__ Wproj,
                                                      float* __restrict__ out) {
    mmagemm_body<Cc>(g_att, Wproj, out);
}

// ---------------------------------------------------------------------------
// Causal flash attention with tf32 mma.sync.
// Grid (T/64, NH, B), 128 threads = 4 warps, 16 Q rows per warp.
// S = Q K^T and O += P V on tensor pipe; online softmax in registers.
// Smem: Qs[64][68], Ks[64][68], Vs[64][72], Ps[64][68]  (70,656 B).
// All fragment LDS patterns conflict-free (addr mod 32 covers 0..31).
// ---------------------------------------------------------------------------
static constexpr int LQ = 68, LK2 = 68, LV = 72, LP = 68;
static constexpr int SMEM_ATTN2 = (64 * (LQ + LK2 + LV + LP)) * (int)sizeof(float);  // 70656

__global__ __launch_bounds__(128) void k_attn_mma() {
    extern __shared__ float sm[];
    float* Qs = sm;                  // [64][LQ]
    float* Ks = Qs + 64 * LQ;        // [64][LK2]
    float* Vs = Ks + 64 * LK2;       // [64][LV]
    float* Ps = Vs + 64 * LV;        // [64][LP]

    const int b    = blockIdx.z;
    const int h    = blockIdx.y;
    const int q0   = blockIdx.x * 64;
    const int tid  = threadIdx.x;
    const int warp = tid >> 5;
    const int lane = tid & 31;
    const int g    = lane >> 2;   // groupID (row within 8)
    const int t    = lane & 3;    // threadInGroup (k / col-pair select)
    const int m0   = warp * 16;   // this warp's first Q row (local)
    const size_t base = (size_t)b * Tt * C3;

    // Load Q tile [64][64] -> Qs (stride LQ)
#pragma unroll
    for (int u = 0; u < 8; u++) {
        int i  = tid + u * 128;
        int r  = i >> 4;
        int d4 = (i & 15) << 2;
        *(float4*)&Qs[r * LQ + d4] =
            *(const float4*)&g_qkv[base + (size_t)(q0 + r) * C3 + h * HD + d4];
    }

    float oa[8][4];
#pragma unroll
    for (int j = 0; j < 8; j++)
#pragma unroll
        for (int r = 0; r < 4; r++) oa[j][r] = 0.f;
    float mrow0 = -1e30f, mrow1 = -1e30f, lrow0 = 0.f, lrow1 = 0.f;

    const int ntiles = (q0 >> 6) + 1;  // causal

    for (int kt = 0; kt < ntiles; kt++) {
        const int k0 = kt * 64;
        // Load K, V tiles
#pragma unroll
        for (int u = 0; u < 8; u++) {
            int i  = tid + u * 128;
            int r  = i >> 4;
            int d4 = (i & 15) << 2;
            const float* src = &g_qkv[base + (size_t)(k0 + r) * C3 + Cc + h * HD + d4];
            *(float4*)&Ks[r * LK2 + d4] = *(const float4*)src;
            *(float4*)&Vs[r * LV + d4]  = *(const float4*)(src + Cc);
        }
        __syncthreads();

        // ---- S = Q K^T (rows m0..m0+15, all 64 cols) ----
        float sa[8][4];
#pragma unroll
        for (int j = 0; j < 8; j++)
#pragma unroll
            for (int r = 0; r < 4; r++) sa[j][r] = 0.f;

#pragma unroll
        for (int ks = 0; ks < 8; ks++) {
            const int kb = ks * 8 + t;
            uint32_t a0 = to_tf32(Qs[(m0 + g) * LQ + kb]);
            uint32_t a1 = to_tf32(Qs[(m0 + g + 8) * LQ + kb]);
            uint32_t a2 = to_tf32(Qs[(m0 + g) * LQ + kb + 4]);
            uint32_t a3 = to_tf32(Qs[(m0 + g + 8) * LQ + kb + 4]);
#pragma unroll
            for (int j = 0; j < 8; j++) {
                uint32_t b0 = to_tf32(Ks[(j * 8 + g) * LK2 + kb]);
                uint32_t b1 = to_tf32(Ks[(j * 8 + g) * LK2 + kb + 4]);
                mma_tf32(sa[j], a0, a1, a2, a3, b0, b1);
            }
        }

        // ---- scale + causal mask + online softmax ----
        const bool diag = (k0 == q0);
        const int r0 = m0 + g, r1 = r0 + 8;  // local rows
        float mx0 = -1e30f, mx1 = -1e30f;
#pragma unroll
        for (int j = 0; j < 8; j++) {
            const int c0 = j * 8 + 2 * t, c1 = c0 + 1;  // local cols
            sa[j][0] *= 0.125f; sa[j][1] *= 0.125f;
            sa[j][2] *= 0.125f; sa[j][3] *= 0.125f;
            if (diag) {
                if (c0 > r0) sa[j][0] = -1e30f;
                if (c1 > r0) sa[j][1] = -1e30f;
                if (c0 > r1) sa[j][2] = -1e30f;
                if (c1 > r1) sa[j][3] = -1e30f;
            }
            mx0 = fmaxf(mx0, fmaxf(sa[j][0], sa[j][1]));
            mx1 = fmaxf(mx1, fmaxf(sa[j][2], sa[j][3]));
        }
        // row max across quad (lanes g*4+t, t=0..3)
#pragma unroll
        for (int off = 1; off <= 2; off <<= 1) {
            mx0 = fmaxf(mx0, __shfl_xor_sync(0xffffffffu, mx0, off));
            mx1 = fmaxf(mx1, __shfl_xor_sync(0xffffffffu, mx1, off));
        }
        const float mn0 = fmaxf(mrow0, mx0);
        const float mn1 = fmaxf(mrow1, mx1);
        const float scl0 = __expf(mrow0 - mn0);
        const float scl1 = __expf(mrow1 - mn1);
        mrow0 = mn0; mrow1 = mn1;

        float sum0 = 0.f, sum1 = 0.f;
#pragma unroll
        for (int j = 0; j < 8; j++) {
            const int c0 = j * 8 + 2 * t;
            float p00 = __expf(sa[j][0] - mn0);
            float p01 = __expf(sa[j][1] - mn0);
            float p10 = __expf(sa[j][2] - mn1);
            float p11 = __expf(sa[j][3] - mn1);
            sum0 += p00 + p01;
            sum1 += p10 + p11;
            *(float2*)&Ps[r0 * LP + c0] = make_float2(p00, p01);
            *(float2*)&Ps[r1 * LP + c0] = make_float2(p10, p11);
        }
#pragma unroll
        for (int off = 1; off <= 2; off <<= 1) {
            sum0 += __shfl_xor_sync(0xffffffffu, sum0, off);
            sum1 += __shfl_xor_sync(0xffffffffu, sum1, off);
        }
        lrow0 = lrow0 * scl0 + sum0;
        lrow1 = lrow1 * scl1 + sum1;
#pragma unroll
        for (int j = 0; j < 8; j++) {
            oa[j][0] *= scl0; oa[j][1] *= scl0;
            oa[j][2] *= scl1; oa[j][3] *= scl1;
        }
        __syncwarp();  // Ps rows of this warp written by this warp only

        // ---- O += P V ----
#pragma unroll
        for (int kc = 0; kc < 8; kc++) {
            const int kb = kc * 8 + t;
            uint32_t a0 = to_tf32(Ps[(m0 + g) * LP + kb]);
            uint32_t a1 = to_tf32(Ps[(m0 + g + 8) * LP + kb]);
            uint32_t a2 = to_tf32(Ps[(m0 + g) * LP + kb + 4]);
            uint32_t a3 = to_tf32(Ps[(m0 + g + 8) * LP + kb + 4]);
#pragma unroll
            for (int j = 0; j < 8; j++) {
                uint32_t b0 = to_tf32(Vs[kb * LV + j * 8 + g]);
                uint32_t b1 = to_tf32(Vs[(kb + 4) * LV + j * 8 + g]);
                mma_tf32(oa[j], a0, a1, a2, a3, b0, b1);
            }
        }
        __syncthreads();  // protect Ks/Vs before next tile
    }

    // ---- normalize + write out ([b,t,c] layout, transpose folded) ----
    const float inv0 = 1.f / lrow0;
    const float inv1 = 1.f / lrow1;
    const int gr0 = q0 + m0 + g, gr1 = gr0 + 8;
#pragma unroll
    for (int j = 0; j < 8; j++) {
        const int col = h * HD + j * 8 + 2 * t;
        *(float2*)&g_att[(size_t)(b * Tt + gr0) * Cc + col] =
            make_float2(oa[j][0] * inv0, oa[j][1] * inv0);
        *(float2*)&g_att[(size_t)(b * Tt + gr1) * Cc + col] =
            make_float2(oa[j][2] * inv1, oa[j][3] * inv1);
    }
}

// ---------------------------------------------------------------------------
// Launch: qkv GEMM (mma) -> attention (mma) -> proj GEMM (mma)
// Inputs (metadata order): x, mask (ignored; causality analytic), Wqkv, Wproj
// ---------------------------------------------------------------------------
extern "C" void kernel_launch(void* const* d_in, const int* in_sizes, int n_in,
                              void* d_out, int out_size) {
    (void)in_sizes; (void)n_in; (void)out_size;
    const float* x     = (const float*)d_in[0];
    const float* Wqkv  = (const float*)d_in[2];
    const float* Wproj = (const float*)d_in[3];
    float* out = (float*)d_out;

    cudaFuncSetAttribute(k_attn_mma, cudaFuncAttributeMaxDynamicSharedMemorySize, SMEM_ATTN2);

    k_mmagemm_qkv<<<dim3(C3 / BN, MM / BM), 256, GSMQ>>>(x, Wqkv);
    k_attn_mma<<<dim3(Tt / 64, NH, Bb), 128, SMEM_ATTN2>>>();
    k_mmagemm_proj<<<dim3(Cc / BN, MM / BM), 256, GSMQ>>>(Wproj, out);
}